// round 14
// baseline (speedup 1.0000x reference)
#include <cuda_runtime.h>
#include <cuda_bf16.h>
#include <math.h>
#include <stdint.h>

#define B_   2048
#define S_   61
#define D_   768
#define H_   512
#define L_   23
#define MTOT (B_ * S_)   // 124928 = 976 * 128

#define HEAD_TOK 1
#define TAIL_TOK 2

// ---------------- scratch globals (no allocation allowed) -------------------
__device__ float         g_buf[MTOT];
__device__ __nv_bfloat16 W1hi[H_ * D_];
__device__ __nv_bfloat16 W1lo[H_ * D_];

// ---------------- helpers ----------------------------------------------------
__device__ __forceinline__ uint32_t smem_u32(const void* p) {
    uint32_t a;
    asm("{ .reg .u64 t; cvta.to.shared.u64 t, %1; cvt.u32.u64 %0, t; }"
        : "=r"(a) : "l"(p));
    return a;
}
__device__ __forceinline__ void cp16(uint32_t dst, const void* src) {
    asm volatile("cp.async.cg.shared.global [%0], [%1], 16;"
                 :: "r"(dst), "l"(src) : "memory");
}
__device__ __forceinline__ void ldsm4(uint32_t* d, uint32_t addr) {
    asm volatile("ldmatrix.sync.aligned.m8n8.x4.shared.b16 {%0,%1,%2,%3}, [%4];"
                 : "=r"(d[0]), "=r"(d[1]), "=r"(d[2]), "=r"(d[3]) : "r"(addr));
}
__device__ __forceinline__ void mma16816(float* c, const uint32_t* a,
                                         uint32_t b0, uint32_t b1) {
    asm volatile(
        "mma.sync.aligned.m16n8k16.row.col.f32.bf16.bf16.f32 "
        "{%0,%1,%2,%3}, {%4,%5,%6,%7}, {%8,%9}, {%0,%1,%2,%3};"
        : "+f"(c[0]), "+f"(c[1]), "+f"(c[2]), "+f"(c[3])
        : "r"(a[0]), "r"(a[1]), "r"(a[2]), "r"(a[3]), "r"(b0), "r"(b1));
}

// ---------------------------------------------------------------------------
// prep_kernel: split W1 fp32 -> bf16 hi/lo
// ---------------------------------------------------------------------------
__global__ void prep_kernel(const float* __restrict__ W1) {
    int i = blockIdx.x * 256 + threadIdx.x;          // over H_*D_/4 float4s
    float4 x = reinterpret_cast<const float4*>(W1)[i];
    float v[4] = {x.x, x.y, x.z, x.w};
    unsigned short hs[4], ls[4];
#pragma unroll
    for (int j = 0; j < 4; ++j) {
        __nv_bfloat16 h = __float2bfloat16(v[j]);
        __nv_bfloat16 l = __float2bfloat16(v[j] - __bfloat162float(h));
        hs[j] = __bfloat16_as_ushort(h);
        ls[j] = __bfloat16_as_ushort(l);
    }
    uint2 hp = make_uint2((uint32_t)hs[0] | ((uint32_t)hs[1] << 16),
                          (uint32_t)hs[2] | ((uint32_t)hs[3] << 16));
    uint2 lp = make_uint2((uint32_t)ls[0] | ((uint32_t)ls[1] << 16),
                          (uint32_t)ls[2] | ((uint32_t)ls[3] << 16));
    *reinterpret_cast<uint2*>(&W1hi[4 * (size_t)i]) = hp;
    *reinterpret_cast<uint2*>(&W1lo[4 * (size_t)i]) = lp;
}

// ---------------------------------------------------------------------------
// gate_kernel: HMMA (mma.sync bf16, 3-pass hi/lo split) fused gate GEMM
//   H[128,512] = Vtile[128,768] @ W1^T ; g = w2 . tanh(H + b1) + b2
// 512 threads, 16 warps as 4m x 4n; warp tile m32 x n32 (2 mt x 4 nt).
// 4 N-chunks of 128; K stages of 64, double-buffered smem.
// ---------------------------------------------------------------------------
#define RS      144                  // smem row stride bytes (64 bf16 + 16B pad)
#define ABYTES  (128 * RS)           // 18432 per matrix
#define BUFB    (4 * ABYTES)         // Ahi, Alo, Bhi, Blo = 73728 per stage
#define OFF_W2  0
#define OFF_B1  2048
#define OFF_GS  4096                 // 512 floats (4 x 128)
#define OFF_BUF 8192
#define GATE_SMEM (OFF_BUF + 2 * BUFB)   // 155648

__global__ __launch_bounds__(512, 1)
void gate_kernel(const float* __restrict__ V,
                 const float* __restrict__ B1,
                 const float* __restrict__ W2,
                 const float* __restrict__ B2)
{
    extern __shared__ char sm[];
    const uint32_t sb = smem_u32(sm);
    const int tid  = threadIdx.x;
    const int wid  = tid >> 5;
    const int lane = tid & 31;
    const int wm   = wid >> 2;       // 0..3  (m direction, 32 rows each)
    const int wn   = wid & 3;        // 0..3  (n direction, 32 cols each)
    const int row0 = blockIdx.x * 128;

    float* w2s = reinterpret_cast<float*>(sm + OFF_W2);
    float* b1s = reinterpret_cast<float*>(sm + OFF_B1);
    float* gs  = reinterpret_cast<float*>(sm + OFF_GS);

    for (int i = tid; i < H_; i += 512) { w2s[i] = W2[i]; b1s[i] = B1[i]; }
    if (tid < 512) gs[tid] = 0.0f;
    __syncthreads();

    // ldmatrix per-thread address components
    const int a_m  = (lane & 7) + ((lane >> 3) & 1) * 8;
    const int a_k2 = (lane >> 4) * 16;
    const int b_n  = (lane & 7) + (lane >> 4) * 8;
    const int b_k2 = ((lane >> 3) & 1) * 16;
    const uint32_t aoff = (uint32_t)((wm * 32 + a_m) * RS) + (uint32_t)a_k2;
    const uint32_t boff = (uint32_t)((wn * 32 + b_n) * RS) + (uint32_t)b_k2;

    float4 areg[4];

#pragma unroll 1
    for (int nc = 0; nc < 4; ++nc) {
        float c[2][4][4];
#pragma unroll
        for (int mt = 0; mt < 2; ++mt)
#pragma unroll
            for (int nt = 0; nt < 4; ++nt)
#pragma unroll
                for (int e = 0; e < 4; ++e) c[mt][nt][e] = 0.0f;

        // ---- prologue: load stage 0 ----
        {
            const int k0 = 0, n0 = nc * 128;
#pragma unroll
            for (int it = 0; it < 2; ++it) {
                int v = tid + it * 512, r = v >> 3, j = v & 7;
                uint32_t d = sb + OFF_BUF + 2u * ABYTES + (uint32_t)(r * RS + j * 16);
                cp16(d,                     W1hi + (size_t)(n0 + r) * D_ + k0 + j * 8);
                cp16(d + (uint32_t)ABYTES,  W1lo + (size_t)(n0 + r) * D_ + k0 + j * 8);
            }
            asm volatile("cp.async.commit_group;" ::: "memory");
#pragma unroll
            for (int it = 0; it < 4; ++it) {
                int v = tid + it * 512, r = v >> 4, c4 = v & 15;
                areg[it] = *reinterpret_cast<const float4*>(
                    V + (size_t)(row0 + r) * D_ + k0 + c4 * 4);
            }
#pragma unroll
            for (int it = 0; it < 4; ++it) {
                int v = tid + it * 512, r = v >> 4, c4 = v & 15;
                float f[4] = {areg[it].x, areg[it].y, areg[it].z, areg[it].w};
                unsigned short hs[4], ls[4];
#pragma unroll
                for (int j = 0; j < 4; ++j) {
                    __nv_bfloat16 h = __float2bfloat16(f[j]);
                    __nv_bfloat16 l = __float2bfloat16(f[j] - __bfloat162float(h));
                    hs[j] = __bfloat16_as_ushort(h); ls[j] = __bfloat16_as_ushort(l);
                }
                uint2 hp = make_uint2((uint32_t)hs[0] | ((uint32_t)hs[1] << 16),
                                      (uint32_t)hs[2] | ((uint32_t)hs[3] << 16));
                uint2 lp = make_uint2((uint32_t)ls[0] | ((uint32_t)ls[1] << 16),
                                      (uint32_t)ls[2] | ((uint32_t)ls[3] << 16));
                char* base = sm + OFF_BUF + r * RS + c4 * 8;
                *reinterpret_cast<uint2*>(base)          = hp;
                *reinterpret_cast<uint2*>(base + ABYTES) = lp;
            }
            asm volatile("cp.async.wait_group 0;" ::: "memory");
            __syncthreads();
        }

        // ---- main loop over 12 K-stages ----
#pragma unroll 1
        for (int s = 0; s < 12; ++s) {
            const uint32_t curOff = OFF_BUF + (uint32_t)(s & 1) * BUFB;
            const uint32_t nxtOff = OFF_BUF + (uint32_t)((s + 1) & 1) * BUFB;

            if (s < 11) {
                const int k0 = (s + 1) * 64, n0 = nc * 128;
#pragma unroll
                for (int it = 0; it < 2; ++it) {
                    int v = tid + it * 512, r = v >> 3, j = v & 7;
                    uint32_t d = sb + nxtOff + 2u * ABYTES + (uint32_t)(r * RS + j * 16);
                    cp16(d,                    W1hi + (size_t)(n0 + r) * D_ + k0 + j * 8);
                    cp16(d + (uint32_t)ABYTES, W1lo + (size_t)(n0 + r) * D_ + k0 + j * 8);
                }
                asm volatile("cp.async.commit_group;" ::: "memory");
#pragma unroll
                for (int it = 0; it < 4; ++it) {
                    int v = tid + it * 512, r = v >> 4, c4 = v & 15;
                    areg[it] = *reinterpret_cast<const float4*>(
                        V + (size_t)(row0 + r) * D_ + k0 + c4 * 4);
                }
            }

            // ---- compute 4 x k16 from current buffers ----
            const uint32_t Ah = sb + curOff;
            const uint32_t Bh = sb + curOff + 2u * ABYTES;
#pragma unroll
            for (int kk = 0; kk < 4; ++kk) {
                const uint32_t kb = (uint32_t)(kk * 32);
                uint32_t ah[2][4];
#pragma unroll
                for (int mt = 0; mt < 2; ++mt)
                    ldsm4(ah[mt], Ah + aoff + (uint32_t)(mt * 16 * RS) + kb);
                uint32_t bh[2][4];
#pragma unroll
                for (int p = 0; p < 2; ++p)
                    ldsm4(bh[p], Bh + boff + (uint32_t)(p * 16 * RS) + kb);
                // hi * hi
#pragma unroll
                for (int mt = 0; mt < 2; ++mt)
#pragma unroll
                    for (int nt = 0; nt < 4; ++nt)
                        mma16816(c[mt][nt], ah[mt],
                                 bh[nt >> 1][(nt & 1) * 2], bh[nt >> 1][(nt & 1) * 2 + 1]);
                // hi * lo
                uint32_t bl[2][4];
#pragma unroll
                for (int p = 0; p < 2; ++p)
                    ldsm4(bl[p], Bh + (uint32_t)ABYTES + boff + (uint32_t)(p * 16 * RS) + kb);
#pragma unroll
                for (int mt = 0; mt < 2; ++mt)
#pragma unroll
                    for (int nt = 0; nt < 4; ++nt)
                        mma16816(c[mt][nt], ah[mt],
                                 bl[nt >> 1][(nt & 1) * 2], bl[nt >> 1][(nt & 1) * 2 + 1]);
                // lo * hi
                uint32_t al[2][4];
#pragma unroll
                for (int mt = 0; mt < 2; ++mt)
                    ldsm4(al[mt], Ah + (uint32_t)ABYTES + aoff + (uint32_t)(mt * 16 * RS) + kb);
#pragma unroll
                for (int mt = 0; mt < 2; ++mt)
#pragma unroll
                    for (int nt = 0; nt < 4; ++nt)
                        mma16816(c[mt][nt], al[mt],
                                 bh[nt >> 1][(nt & 1) * 2], bh[nt >> 1][(nt & 1) * 2 + 1]);
            }

            if (s < 11) {
#pragma unroll
                for (int it = 0; it < 4; ++it) {
                    int v = tid + it * 512, r = v >> 4, c4 = v & 15;
                    float f[4] = {areg[it].x, areg[it].y, areg[it].z, areg[it].w};
                    unsigned short hs[4], ls[4];
#pragma unroll
                    for (int j = 0; j < 4; ++j) {
                        __nv_bfloat16 h = __float2bfloat16(f[j]);
                        __nv_bfloat16 l = __float2bfloat16(f[j] - __bfloat162float(h));
                        hs[j] = __bfloat16_as_ushort(h); ls[j] = __bfloat16_as_ushort(l);
                    }
                    uint2 hp = make_uint2((uint32_t)hs[0] | ((uint32_t)hs[1] << 16),
                                          (uint32_t)hs[2] | ((uint32_t)hs[3] << 16));
                    uint2 lp = make_uint2((uint32_t)ls[0] | ((uint32_t)ls[1] << 16),
                                          (uint32_t)ls[2] | ((uint32_t)ls[3] << 16));
                    char* base = sm + nxtOff + r * RS + c4 * 8;
                    *reinterpret_cast<uint2*>(base)          = hp;
                    *reinterpret_cast<uint2*>(base + ABYTES) = lp;
                }
                asm volatile("cp.async.wait_group 0;" ::: "memory");
            }
            __syncthreads();
        }

        // ---- epilogue: accumulate partial g into gs ----
#pragma unroll
        for (int mt = 0; mt < 2; ++mt) {
            float s0 = 0.0f, s1 = 0.0f;
#pragma unroll
            for (int nt = 0; nt < 4; ++nt) {
                int n = nc * 128 + wn * 32 + nt * 8 + (lane & 3) * 2;
                float w0 = w2s[n],     w1v = w2s[n + 1];
                float q0 = b1s[n],     q1  = b1s[n + 1];
                s0 += w0 * tanhf(c[mt][nt][0] + q0) + w1v * tanhf(c[mt][nt][1] + q1);
                s1 += w0 * tanhf(c[mt][nt][2] + q0) + w1v * tanhf(c[mt][nt][3] + q1);
            }
            s0 += __shfl_xor_sync(0xffffffffu, s0, 1);
            s0 += __shfl_xor_sync(0xffffffffu, s0, 2);
            s1 += __shfl_xor_sync(0xffffffffu, s1, 1);
            s1 += __shfl_xor_sync(0xffffffffu, s1, 2);
            if ((lane & 3) == 0) {
                int m = wm * 32 + mt * 16 + (lane >> 2);
                gs[wn * 128 + m]     += s0;
                gs[wn * 128 + m + 8] += s1;
            }
        }
    }

    __syncthreads();
    if (tid < 128)
        g_buf[row0 + tid] = gs[tid] + gs[128 + tid] + gs[256 + tid] + gs[384 + tid]
                          + B2[0];
}

// ---------------------------------------------------------------------------
// attn_kernel: per-batch attention + classifier. Fuses the V DRAM read with
// the score pass (dot with Th/Tt while staging V into smem); entity pass
// then runs from smem. Uses ms == 1/61 identity to skip the first softmax.
// ---------------------------------------------------------------------------
#define AOFF_V   0
#define AOFF_TH  (S_ * D_ * 4)              // 187392
#define AOFF_TT  (AOFF_TH + D_ * 4)
#define AOFF_ENT (AOFF_TT + D_ * 4)
#define AOFF_SCH (AOFF_ENT + 2 * D_ * 4)
#define AOFF_SCT (AOFF_SCH + 256)
#define AOFF_G   (AOFF_SCT + 256)
#define AOFF_WH  (AOFF_G + 256)
#define AOFF_WT  (AOFF_WH + 256)
#define ATTN_SMEM (AOFF_WT + 256)           // 200960

__global__ __launch_bounds__(256, 1)
void attn_kernel(const float* __restrict__ T,
                 const float* __restrict__ V,
                 const int*   __restrict__ ids,
                 const float* __restrict__ CW,
                 const float* __restrict__ CB,
                 float*       __restrict__ out)
{
    extern __shared__ char sm[];
    float* Vs   = reinterpret_cast<float*>(sm + AOFF_V);
    float* Th   = reinterpret_cast<float*>(sm + AOFF_TH);
    float* Tt   = reinterpret_cast<float*>(sm + AOFF_TT);
    float* ent  = reinterpret_cast<float*>(sm + AOFF_ENT);
    float* sc_h = reinterpret_cast<float*>(sm + AOFF_SCH);
    float* sc_t = reinterpret_cast<float*>(sm + AOFF_SCT);
    float* gsA  = reinterpret_cast<float*>(sm + AOFF_G);
    float* wh   = reinterpret_cast<float*>(sm + AOFF_WH);
    float* wt   = reinterpret_cast<float*>(sm + AOFF_WT);
    __shared__ int hidx, tidx;

    const int b   = blockIdx.x;
    const int tid = threadIdx.x;
    const int warp = tid >> 5, lane = tid & 31;

    if (tid == 0) { hidx = 0; tidx = 0; }
    __syncthreads();

    if (tid < S_) {
        int id = ids[b * S_ + tid];
        if (id == HEAD_TOK) hidx = tid;
        if (id == TAIL_TOK) tidx = tid;
        gsA[tid] = g_buf[b * S_ + tid];
    }
    __syncthreads();

    const int hq = hidx, tq = tidx;
    for (int d = tid; d < D_; d += 256) {
        Th[d] = T[((size_t)b * S_ + hq) * D_ + d];
        Tt[d] = T[((size_t)b * S_ + tq) * D_ + d];
    }
    __syncthreads();

    // fused: stream V into smem while computing the two score rows
    for (int k = warp; k < S_; k += 8) {
        const float* vk = V + ((size_t)b * S_ + k) * D_;
        float* vd = Vs + k * D_;
        float sh = 0.0f, st = 0.0f;
#pragma unroll 6
        for (int d = lane; d < D_; d += 32) {
            float v = vk[d];
            vd[d] = v;
            sh = fmaf(Th[d], v, sh);
            st = fmaf(Tt[d], v, st);
        }
#pragma unroll
        for (int o = 16; o; o >>= 1) {
            sh += __shfl_xor_sync(0xffffffffu, sh, o);
            st += __shfl_xor_sync(0xffffffffu, st, o);
        }
        if (lane == 0) { sc_h[k] = sh; sc_t[k] = st; }
    }
    __syncthreads();

    // gated softmax: a = (scores*(1-g) + g/61) / sqrt(768)
    if (warp < 2) {
        const float* sc = warp ? sc_t : sc_h;
        float*       w  = warp ? wt   : wh;
        const float scale = sqrtf((float)D_);
        const float inv61 = 1.0f / (float)S_;

        int k0 = lane, k1 = lane + 32;
        float a0 = -1e30f, a1 = -1e30f;
        if (k0 < S_) a0 = (sc[k0] * (1.0f - gsA[k0]) + gsA[k0] * inv61) / scale;
        if (k1 < S_) a1 = (sc[k1] * (1.0f - gsA[k1]) + gsA[k1] * inv61) / scale;
        float m = fmaxf(a0, a1);
#pragma unroll
        for (int o = 16; o; o >>= 1) m = fmaxf(m, __shfl_xor_sync(0xffffffffu, m, o));
        float e0 = (k0 < S_) ? expf(a0 - m) : 0.0f;
        float e1 = (k1 < S_) ? expf(a1 - m) : 0.0f;
        float s = e0 + e1;
#pragma unroll
        for (int o = 16; o; o >>= 1) s += __shfl_xor_sync(0xffffffffu, s, o);
        float inv = 1.0f / s;
        if (k0 < S_) w[k0] = e0 * inv;
        if (k1 < S_) w[k1] = e1 * inv;
    }
    __syncthreads();

    // entity vector: weighted sums over V keys (from smem V)
    for (int d = tid; d < D_; d += 256) {
        float ah = 0.0f, at = 0.0f;
        const float* vb = Vs + d;
#pragma unroll 4
        for (int k = 0; k < S_; ++k) {
            float v = vb[k * D_];
            ah = fmaf(wh[k], v, ah);
            at = fmaf(wt[k], v, at);
        }
        ent[d]      = ah;
        ent[D_ + d] = at;
    }
    __syncthreads();

    // classifier
    for (int l = warp; l < L_; l += 8) {
        const float* cw = CW + (size_t)l * (2 * D_);
        float s = 0.0f;
        for (int d = lane; d < 2 * D_; d += 32)
            s = fmaf(cw[d], ent[d], s);
#pragma unroll
        for (int o = 16; o; o >>= 1) s += __shfl_xor_sync(0xffffffffu, s, o);
        if (lane == 0) out[(size_t)b * L_ + l] = s + CB[l];
    }
}

// ---------------------------------------------------------------------------
extern "C" void kernel_launch(void* const* d_in, const int* in_sizes, int n_in,
                              void* d_out, int out_size)
{
    const float* T_recon = (const float*)d_in[0];
    const float* V_recon = (const float*)d_in[1];
    const int*   ids     = (const int*)  d_in[2];
    const float* fc1_w   = (const float*)d_in[3];
    const float* fc1_b   = (const float*)d_in[4];
    const float* fc2_w   = (const float*)d_in[5];
    const float* fc2_b   = (const float*)d_in[6];
    const float* clf_w   = (const float*)d_in[7];
    const float* clf_b   = (const float*)d_in[8];
    float* out = (float*)d_out;

    cudaFuncSetAttribute(gate_kernel,
                         cudaFuncAttributeMaxDynamicSharedMemorySize, GATE_SMEM);
    cudaFuncSetAttribute(attn_kernel,
                         cudaFuncAttributeMaxDynamicSharedMemorySize, ATTN_SMEM);

    prep_kernel<<<H_ * D_ / 4 / 256, 256>>>(fc1_w);
    gate_kernel<<<MTOT / 128, 512, GATE_SMEM>>>(V_recon, fc1_b, fc2_w, fc2_b);
    attn_kernel<<<B_, 256, ATTN_SMEM>>>(T_recon, V_recon, ids, clf_w, clf_b, out);
}

// round 15
// speedup vs baseline: 1.4048x; 1.4048x over previous
#include <cuda_runtime.h>
#include <cuda_fp16.h>
#include <math.h>
#include <stdint.h>

#define B_   2048
#define S_   61
#define D_   768
#define H_   512
#define L_   23
#define MTOT (B_ * S_)   // 124928 = 976 * 128

#define HEAD_TOK 1
#define TAIL_TOK 2

// ---------------- scratch globals (no allocation allowed) -------------------
__device__ float  g_buf[MTOT];
__device__ __half W1h[H_ * D_];

// ---------------- helpers ----------------------------------------------------
__device__ __forceinline__ uint32_t smem_u32(const void* p) {
    uint32_t a;
    asm("{ .reg .u64 t; cvta.to.shared.u64 t, %1; cvt.u32.u64 %0, t; }"
        : "=r"(a) : "l"(p));
    return a;
}
__device__ __forceinline__ void cp16(uint32_t dst, const void* src) {
    asm volatile("cp.async.cg.shared.global [%0], [%1], 16;"
                 :: "r"(dst), "l"(src) : "memory");
}
__device__ __forceinline__ void ldsm4(uint32_t* d, uint32_t addr) {
    asm volatile("ldmatrix.sync.aligned.m8n8.x4.shared.b16 {%0,%1,%2,%3}, [%4];"
                 : "=r"(d[0]), "=r"(d[1]), "=r"(d[2]), "=r"(d[3]) : "r"(addr));
}
__device__ __forceinline__ void mma16816(float* c, const uint32_t* a,
                                         uint32_t b0, uint32_t b1) {
    asm volatile(
        "mma.sync.aligned.m16n8k16.row.col.f32.f16.f16.f32 "
        "{%0,%1,%2,%3}, {%4,%5,%6,%7}, {%8,%9}, {%0,%1,%2,%3};"
        : "+f"(c[0]), "+f"(c[1]), "+f"(c[2]), "+f"(c[3])
        : "r"(a[0]), "r"(a[1]), "r"(a[2]), "r"(a[3]), "r"(b0), "r"(b1));
}

// ---------------------------------------------------------------------------
// prep_kernel: W1 fp32 -> fp16 (single precision-level; A side carries hi/lo)
// ---------------------------------------------------------------------------
__global__ void prep_kernel(const float* __restrict__ W1) {
    int i = blockIdx.x * 256 + threadIdx.x;          // over H_*D_/4 float4s
    float4 x = reinterpret_cast<const float4*>(W1)[i];
    __half2 h0 = make_half2(__float2half(x.x), __float2half(x.y));
    __half2 h1 = make_half2(__float2half(x.z), __float2half(x.w));
    uint2 hp = make_uint2(*reinterpret_cast<uint32_t*>(&h0),
                          *reinterpret_cast<uint32_t*>(&h1));
    *reinterpret_cast<uint2*>(&W1h[4 * (size_t)i]) = hp;
}

// ---------------------------------------------------------------------------
// gate_kernel: HMMA fp16 2-pass (A_hi*B + A_lo*B) fused gate GEMM
//   H[128,512] = Vtile[128,768] @ W1^T ; g = w2 . tanh(H + b1) + b2
// 256 threads, 8 warps (2m x 4n); warp tile m64 x n32 (4 mt x 4 nt).
// 4 N-chunks of 128; K stages of 64, double-buffered smem.
// ---------------------------------------------------------------------------
#define RS      144                  // smem row stride bytes (64 fp16 + 16B pad)
#define ABYTES  (128 * RS)           // 18432 per matrix
#define BUFB    (3 * ABYTES)         // Ahi, Alo, Bh = 55296 per stage
#define OFF_W2  0
#define OFF_B1  2048
#define OFF_GS  4096                 // 512 floats (4 x 128)
#define OFF_BUF 8192
#define GATE_SMEM (OFF_BUF + 2 * BUFB)   // 118784

__global__ __launch_bounds__(256, 1)
void gate_kernel(const float* __restrict__ V,
                 const float* __restrict__ B1,
                 const float* __restrict__ W2,
                 const float* __restrict__ B2)
{
    extern __shared__ char sm[];
    const uint32_t sb = smem_u32(sm);
    const int tid  = threadIdx.x;
    const int wid  = tid >> 5;
    const int lane = tid & 31;
    const int wm   = wid >> 2;       // 0..1  (m direction, 64 rows each)
    const int wn   = wid & 3;        // 0..3  (n direction, 32 cols each)
    const int row0 = blockIdx.x * 128;

    float* w2s = reinterpret_cast<float*>(sm + OFF_W2);
    float* b1s = reinterpret_cast<float*>(sm + OFF_B1);
    float* gs  = reinterpret_cast<float*>(sm + OFF_GS);

    for (int i = tid; i < H_; i += 256) { w2s[i] = W2[i]; b1s[i] = B1[i]; }
    for (int i = tid; i < 512; i += 256) gs[i] = 0.0f;
    __syncthreads();

    // ldmatrix per-thread address components
    const int a_m  = (lane & 7) + ((lane >> 3) & 1) * 8;
    const int a_k2 = (lane >> 4) * 16;
    const int b_n  = (lane & 7) + (lane >> 4) * 8;
    const int b_k2 = ((lane >> 3) & 1) * 16;
    const uint32_t aoff = (uint32_t)((wm * 64 + a_m) * RS) + (uint32_t)a_k2;
    const uint32_t boff = (uint32_t)((wn * 32 + b_n) * RS) + (uint32_t)b_k2;

    float4 areg[8];

#pragma unroll 1
    for (int nc = 0; nc < 4; ++nc) {
        float c[4][4][4];
#pragma unroll
        for (int mt = 0; mt < 4; ++mt)
#pragma unroll
            for (int nt = 0; nt < 4; ++nt)
#pragma unroll
                for (int e = 0; e < 4; ++e) c[mt][nt][e] = 0.0f;

        // ---- prologue: load stage 0 ----
        {
            const int k0 = 0, n0 = nc * 128;
#pragma unroll
            for (int it = 0; it < 4; ++it) {
                int v = tid + it * 256, r = v >> 3, j = v & 7;
                uint32_t d = sb + OFF_BUF + 2u * ABYTES + (uint32_t)(r * RS + j * 16);
                cp16(d, W1h + (size_t)(n0 + r) * D_ + k0 + j * 8);
            }
            asm volatile("cp.async.commit_group;" ::: "memory");
#pragma unroll
            for (int it = 0; it < 8; ++it) {
                int v = tid + it * 256, r = v >> 4, c4 = v & 15;
                areg[it] = *reinterpret_cast<const float4*>(
                    V + (size_t)(row0 + r) * D_ + k0 + c4 * 4);
            }
#pragma unroll
            for (int it = 0; it < 8; ++it) {
                int v = tid + it * 256, r = v >> 4, c4 = v & 15;
                float f[4] = {areg[it].x, areg[it].y, areg[it].z, areg[it].w};
                __half h[4], l[4];
#pragma unroll
                for (int j = 0; j < 4; ++j) {
                    h[j] = __float2half(f[j]);
                    l[j] = __float2half(f[j] - __half2float(h[j]));
                }
                __half2 hp0 = make_half2(h[0], h[1]), hp1 = make_half2(h[2], h[3]);
                __half2 lp0 = make_half2(l[0], l[1]), lp1 = make_half2(l[2], l[3]);
                uint2 hp = make_uint2(*reinterpret_cast<uint32_t*>(&hp0),
                                      *reinterpret_cast<uint32_t*>(&hp1));
                uint2 lp = make_uint2(*reinterpret_cast<uint32_t*>(&lp0),
                                      *reinterpret_cast<uint32_t*>(&lp1));
                char* base = sm + OFF_BUF + r * RS + c4 * 8;
                *reinterpret_cast<uint2*>(base)          = hp;
                *reinterpret_cast<uint2*>(base + ABYTES) = lp;
            }
            asm volatile("cp.async.wait_group 0;" ::: "memory");
            __syncthreads();
        }

        // ---- main loop over 12 K-stages ----
#pragma unroll 1
        for (int s = 0; s < 12; ++s) {
            const uint32_t curOff = OFF_BUF + (uint32_t)(s & 1) * BUFB;
            const uint32_t nxtOff = OFF_BUF + (uint32_t)((s + 1) & 1) * BUFB;

            if (s < 11) {
                const int k0 = (s + 1) * 64, n0 = nc * 128;
#pragma unroll
                for (int it = 0; it < 4; ++it) {
                    int v = tid + it * 256, r = v >> 3, j = v & 7;
                    uint32_t d = sb + nxtOff + 2u * ABYTES + (uint32_t)(r * RS + j * 16);
                    cp16(d, W1h + (size_t)(n0 + r) * D_ + k0 + j * 8);
                }
                asm volatile("cp.async.commit_group;" ::: "memory");
#pragma unroll
                for (int it = 0; it < 8; ++it) {
                    int v = tid + it * 256, r = v >> 4, c4 = v & 15;
                    areg[it] = *reinterpret_cast<const float4*>(
                        V + (size_t)(row0 + r) * D_ + k0 + c4 * 4);
                }
            }

            // ---- compute 4 x k16 from current buffers ----
            const uint32_t Ah = sb + curOff;
            const uint32_t Bh = sb + curOff + 2u * ABYTES;
#pragma unroll
            for (int kk = 0; kk < 4; ++kk) {
                const uint32_t kb = (uint32_t)(kk * 32);
                uint32_t ah[4][4];
#pragma unroll
                for (int mt = 0; mt < 4; ++mt)
                    ldsm4(ah[mt], Ah + aoff + (uint32_t)(mt * 16 * RS) + kb);
                uint32_t bh[2][4];
#pragma unroll
                for (int p = 0; p < 2; ++p)
                    ldsm4(bh[p], Bh + boff + (uint32_t)(p * 16 * RS) + kb);
                // pass 1: A_hi * B
#pragma unroll
                for (int mt = 0; mt < 4; ++mt)
#pragma unroll
                    for (int nt = 0; nt < 4; ++nt)
                        mma16816(c[mt][nt], ah[mt],
                                 bh[nt >> 1][(nt & 1) * 2], bh[nt >> 1][(nt & 1) * 2 + 1]);
                // pass 2: A_lo * B
                uint32_t al[4][4];
#pragma unroll
                for (int mt = 0; mt < 4; ++mt)
                    ldsm4(al[mt], Ah + (uint32_t)ABYTES + aoff + (uint32_t)(mt * 16 * RS) + kb);
#pragma unroll
                for (int mt = 0; mt < 4; ++mt)
#pragma unroll
                    for (int nt = 0; nt < 4; ++nt)
                        mma16816(c[mt][nt], al[mt],
                                 bh[nt >> 1][(nt & 1) * 2], bh[nt >> 1][(nt & 1) * 2 + 1]);
            }

            if (s < 11) {
#pragma unroll
                for (int it = 0; it < 8; ++it) {
                    int v = tid + it * 256, r = v >> 4, c4 = v & 15;
                    float f[4] = {areg[it].x, areg[it].y, areg[it].z, areg[it].w};
                    __half h[4], l[4];
#pragma unroll
                    for (int j = 0; j < 4; ++j) {
                        h[j] = __float2half(f[j]);
                        l[j] = __float2half(f[j] - __half2float(h[j]));
                    }
                    __half2 hp0 = make_half2(h[0], h[1]), hp1 = make_half2(h[2], h[3]);
                    __half2 lp0 = make_half2(l[0], l[1]), lp1 = make_half2(l[2], l[3]);
                    uint2 hp = make_uint2(*reinterpret_cast<uint32_t*>(&hp0),
                                          *reinterpret_cast<uint32_t*>(&hp1));
                    uint2 lp = make_uint2(*reinterpret_cast<uint32_t*>(&lp0),
                                          *reinterpret_cast<uint32_t*>(&lp1));
                    char* base = sm + nxtOff + r * RS + c4 * 8;
                    *reinterpret_cast<uint2*>(base)          = hp;
                    *reinterpret_cast<uint2*>(base + ABYTES) = lp;
                }
                asm volatile("cp.async.wait_group 0;" ::: "memory");
            }
            __syncthreads();
        }

        // ---- epilogue: accumulate partial g into gs ----
#pragma unroll
        for (int mt = 0; mt < 4; ++mt) {
            float s0 = 0.0f, s1 = 0.0f;
#pragma unroll
            for (int nt = 0; nt < 4; ++nt) {
                int n = nc * 128 + wn * 32 + nt * 8 + (lane & 3) * 2;
                float w0 = w2s[n],     w1v = w2s[n + 1];
                float q0 = b1s[n],     q1  = b1s[n + 1];
                s0 += w0 * tanhf(c[mt][nt][0] + q0) + w1v * tanhf(c[mt][nt][1] + q1);
                s1 += w0 * tanhf(c[mt][nt][2] + q0) + w1v * tanhf(c[mt][nt][3] + q1);
            }
            s0 += __shfl_xor_sync(0xffffffffu, s0, 1);
            s0 += __shfl_xor_sync(0xffffffffu, s0, 2);
            s1 += __shfl_xor_sync(0xffffffffu, s1, 1);
            s1 += __shfl_xor_sync(0xffffffffu, s1, 2);
            if ((lane & 3) == 0) {
                int m = wm * 64 + mt * 16 + (lane >> 2);
                gs[wn * 128 + m]     += s0;
                gs[wn * 128 + m + 8] += s1;
            }
        }
    }

    __syncthreads();
    if (tid < 128)
        g_buf[row0 + tid] = gs[tid] + gs[128 + tid] + gs[256 + tid] + gs[384 + tid]
                          + B2[0];
}

// ---------------------------------------------------------------------------
// attn_kernel (R13 version): per-batch attention + classifier, V cached in
// smem. Uses ms == 1/61 identity to skip the first softmax.
// ---------------------------------------------------------------------------
#define AOFF_V   0
#define AOFF_TH  (S_ * D_ * 4)              // 187392
#define AOFF_TT  (AOFF_TH + D_ * 4)
#define AOFF_ENT (AOFF_TT + D_ * 4)
#define AOFF_SCH (AOFF_ENT + 2 * D_ * 4)
#define AOFF_SCT (AOFF_SCH + 256)
#define AOFF_G   (AOFF_SCT + 256)
#define AOFF_WH  (AOFF_G + 256)
#define AOFF_WT  (AOFF_WH + 256)
#define ATTN_SMEM (AOFF_WT + 256)           // 200960

__global__ __launch_bounds__(256, 1)
void attn_kernel(const float* __restrict__ T,
                 const float* __restrict__ V,
                 const int*   __restrict__ ids,
                 const float* __restrict__ CW,
                 const float* __restrict__ CB,
                 float*       __restrict__ out)
{
    extern __shared__ char sm[];
    float* Vs   = reinterpret_cast<float*>(sm + AOFF_V);
    float* Th   = reinterpret_cast<float*>(sm + AOFF_TH);
    float* Tt   = reinterpret_cast<float*>(sm + AOFF_TT);
    float* ent  = reinterpret_cast<float*>(sm + AOFF_ENT);
    float* sc_h = reinterpret_cast<float*>(sm + AOFF_SCH);
    float* sc_t = reinterpret_cast<float*>(sm + AOFF_SCT);
    float* gsA  = reinterpret_cast<float*>(sm + AOFF_G);
    float* wh   = reinterpret_cast<float*>(sm + AOFF_WH);
    float* wt   = reinterpret_cast<float*>(sm + AOFF_WT);
    __shared__ int hidx, tidx;

    const int b   = blockIdx.x;
    const int tid = threadIdx.x;
    const int warp = tid >> 5, lane = tid & 31;

    // V tile -> smem (read V from DRAM exactly once)
    const float4* vsrc = reinterpret_cast<const float4*>(V + (size_t)b * S_ * D_);
    for (int i = tid; i < S_ * D_ / 4; i += 256)
        reinterpret_cast<float4*>(Vs)[i] = vsrc[i];

    if (tid == 0) { hidx = 0; tidx = 0; }
    __syncthreads();

    if (tid < S_) {
        int id = ids[b * S_ + tid];
        if (id == HEAD_TOK) hidx = tid;
        if (id == TAIL_TOK) tidx = tid;
        gsA[tid] = g_buf[b * S_ + tid];
    }
    __syncthreads();

    const int hq = hidx, tq = tidx;
    for (int d = tid; d < D_; d += 256) {
        Th[d] = T[((size_t)b * S_ + hq) * D_ + d];
        Tt[d] = T[((size_t)b * S_ + tq) * D_ + d];
    }
    __syncthreads();

    // raw scores for the two needed query rows (from smem V)
    for (int k = warp; k < S_; k += 8) {
        const float* vk = Vs + k * D_;
        float sh = 0.0f, st = 0.0f;
        for (int d = lane; d < D_; d += 32) {
            float v = vk[d];
            sh = fmaf(Th[d], v, sh);
            st = fmaf(Tt[d], v, st);
        }
#pragma unroll
        for (int o = 16; o; o >>= 1) {
            sh += __shfl_xor_sync(0xffffffffu, sh, o);
            st += __shfl_xor_sync(0xffffffffu, st, o);
        }
        if (lane == 0) { sc_h[k] = sh; sc_t[k] = st; }
    }
    __syncthreads();

    // gated softmax: a = (scores*(1-g) + g/61) / sqrt(768)
    if (warp < 2) {
        const float* sc = warp ? sc_t : sc_h;
        float*       w  = warp ? wt   : wh;
        const float scale = sqrtf((float)D_);
        const float inv61 = 1.0f / (float)S_;

        int k0 = lane, k1 = lane + 32;
        float a0 = -1e30f, a1 = -1e30f;
        if (k0 < S_) a0 = (sc[k0] * (1.0f - gsA[k0]) + gsA[k0] * inv61) / scale;
        if (k1 < S_) a1 = (sc[k1] * (1.0f - gsA[k1]) + gsA[k1] * inv61) / scale;
        float m = fmaxf(a0, a1);
#pragma unroll
        for (int o = 16; o; o >>= 1) m = fmaxf(m, __shfl_xor_sync(0xffffffffu, m, o));
        float e0 = (k0 < S_) ? expf(a0 - m) : 0.0f;
        float e1 = (k1 < S_) ? expf(a1 - m) : 0.0f;
        float s = e0 + e1;
#pragma unroll
        for (int o = 16; o; o >>= 1) s += __shfl_xor_sync(0xffffffffu, s, o);
        float inv = 1.0f / s;
        if (k0 < S_) w[k0] = e0 * inv;
        if (k1 < S_) w[k1] = e1 * inv;
    }
    __syncthreads();

    // entity vector: weighted sums over V keys (from smem V)
    for (int d = tid; d < D_; d += 256) {
        float ah = 0.0f, at = 0.0f;
        const float* vb = Vs + d;
#pragma unroll 4
        for (int k = 0; k < S_; ++k) {
            float v = vb[k * D_];
            ah = fmaf(wh[k], v, ah);
            at = fmaf(wt[k], v, at);
        }
        ent[d]      = ah;
        ent[D_ + d] = at;
    }
    __syncthreads();

    // classifier
    for (int l = warp; l < L_; l += 8) {
        const float* cw = CW + (size_t)l * (2 * D_);
        float s = 0.0f;
        for (int d = lane; d < 2 * D_; d += 32)
            s = fmaf(cw[d], ent[d], s);
#pragma unroll
        for (int o = 16; o; o >>= 1) s += __shfl_xor_sync(0xffffffffu, s, o);
        if (lane == 0) out[(size_t)b * L_ + l] = s + CB[l];
    }
}

// ---------------------------------------------------------------------------
extern "C" void kernel_launch(void* const* d_in, const int* in_sizes, int n_in,
                              void* d_out, int out_size)
{
    const float* T_recon = (const float*)d_in[0];
    const float* V_recon = (const float*)d_in[1];
    const int*   ids     = (const int*)  d_in[2];
    const float* fc1_w   = (const float*)d_in[3];
    const float* fc1_b   = (const float*)d_in[4];
    const float* fc2_w   = (const float*)d_in[5];
    const float* fc2_b   = (const float*)d_in[6];
    const float* clf_w   = (const float*)d_in[7];
    const float* clf_b   = (const float*)d_in[8];
    float* out = (float*)d_out;

    cudaFuncSetAttribute(gate_kernel,
                         cudaFuncAttributeMaxDynamicSharedMemorySize, GATE_SMEM);
    cudaFuncSetAttribute(attn_kernel,
                         cudaFuncAttributeMaxDynamicSharedMemorySize, ATTN_SMEM);

    prep_kernel<<<H_ * D_ / 4 / 256, 256>>>(fc1_w);
    gate_kernel<<<MTOT / 128, 256, GATE_SMEM>>>(V_recon, fc1_b, fc2_w, fc2_b);
    attn_kernel<<<B_, 256, ATTN_SMEM>>>(T_recon, V_recon, ids, clf_w, clf_b, out);
}

// round 16
// speedup vs baseline: 2.0937x; 1.4904x over previous
#include <cuda_runtime.h>
#include <cuda_fp16.h>
#include <math.h>
#include <stdint.h>

#define B_   2048
#define S_   61
#define D_   768
#define H_   512
#define L_   23
#define MTOT (B_ * S_)   // 124928 = 976 * 128

#define HEAD_TOK 1
#define TAIL_TOK 2

// ---------------- scratch globals (no allocation allowed) -------------------
__device__ float  g_buf[MTOT];
__device__ __half W1h[H_ * D_];

// ---------------- helpers ----------------------------------------------------
__device__ __forceinline__ uint32_t smem_u32(const void* p) {
    uint32_t a;
    asm("{ .reg .u64 t; cvta.to.shared.u64 t, %1; cvt.u32.u64 %0, t; }"
        : "=r"(a) : "l"(p));
    return a;
}
__device__ __forceinline__ void cp16(uint32_t dst, const void* src) {
    asm volatile("cp.async.cg.shared.global [%0], [%1], 16;"
                 :: "r"(dst), "l"(src) : "memory");
}
__device__ __forceinline__ void ldsm4(uint32_t* d, uint32_t addr) {
    asm volatile("ldmatrix.sync.aligned.m8n8.x4.shared.b16 {%0,%1,%2,%3}, [%4];"
                 : "=r"(d[0]), "=r"(d[1]), "=r"(d[2]), "=r"(d[3]) : "r"(addr));
}
__device__ __forceinline__ void mma16816(float* c, const uint32_t* a,
                                         uint32_t b0, uint32_t b1) {
    asm volatile(
        "mma.sync.aligned.m16n8k16.row.col.f32.f16.f16.f32 "
        "{%0,%1,%2,%3}, {%4,%5,%6,%7}, {%8,%9}, {%0,%1,%2,%3};"
        : "+f"(c[0]), "+f"(c[1]), "+f"(c[2]), "+f"(c[3])
        : "r"(a[0]), "r"(a[1]), "r"(a[2]), "r"(a[3]), "r"(b0), "r"(b1));
}

// ---------------------------------------------------------------------------
// prep_kernel: W1 fp32 -> fp16
// ---------------------------------------------------------------------------
__global__ void prep_kernel(const float* __restrict__ W1) {
    int i = blockIdx.x * 256 + threadIdx.x;          // over H_*D_/4 float4s
    float4 x = reinterpret_cast<const float4*>(W1)[i];
    __half2 h0 = make_half2(__float2half(x.x), __float2half(x.y));
    __half2 h1 = make_half2(__float2half(x.z), __float2half(x.w));
    uint2 hp = make_uint2(*reinterpret_cast<uint32_t*>(&h0),
                          *reinterpret_cast<uint32_t*>(&h1));
    *reinterpret_cast<uint2*>(&W1h[4 * (size_t)i]) = hp;
}

// ---------------------------------------------------------------------------
// gate_kernel: single-pass fp16 HMMA fused gate GEMM
//   H[128,512] = Vtile[128,768] @ W1^T ; g = w2 . tanh(H + b1) + b2
// 256 threads, 8 warps (2m x 4n); warp tile m64 x n32 (4 mt x 4 nt).
// 4 N-chunks of 128; K stages of 64, double-buffered smem (A fp16, B fp16).
// ---------------------------------------------------------------------------
#define RS      144                  // smem row stride bytes (64 fp16 + 16B pad)
#define ABYTES  (128 * RS)           // 18432 per matrix
#define BUFB    (2 * ABYTES)         // A, B = 36864 per stage
#define OFF_W2  0
#define OFF_B1  2048
#define OFF_GS  4096                 // 512 floats
#define OFF_BUF 8192
#define GATE_SMEM (OFF_BUF + 2 * BUFB)   // 81920

__global__ __launch_bounds__(256, 1)
void gate_kernel(const float* __restrict__ V,
                 const float* __restrict__ B1,
                 const float* __restrict__ W2,
                 const float* __restrict__ B2)
{
    extern __shared__ char sm[];
    const uint32_t sb = smem_u32(sm);
    const int tid  = threadIdx.x;
    const int wid  = tid >> 5;
    const int lane = tid & 31;
    const int wm   = wid >> 2;       // 0..1  (m direction, 64 rows each)
    const int wn   = wid & 3;        // 0..3  (n direction, 32 cols each)
    const int row0 = blockIdx.x * 128;

    float* w2s = reinterpret_cast<float*>(sm + OFF_W2);
    float* b1s = reinterpret_cast<float*>(sm + OFF_B1);
    float* gs  = reinterpret_cast<float*>(sm + OFF_GS);

    for (int i = tid; i < H_; i += 256) { w2s[i] = W2[i]; b1s[i] = B1[i]; }
    for (int i = tid; i < 512; i += 256) gs[i] = 0.0f;
    __syncthreads();

    // ldmatrix per-thread address components
    const int a_m  = (lane & 7) + ((lane >> 3) & 1) * 8;
    const int a_k2 = (lane >> 4) * 16;
    const int b_n  = (lane & 7) + (lane >> 4) * 8;
    const int b_k2 = ((lane >> 3) & 1) * 16;
    const uint32_t aoff = (uint32_t)((wm * 64 + a_m) * RS) + (uint32_t)a_k2;
    const uint32_t boff = (uint32_t)((wn * 32 + b_n) * RS) + (uint32_t)b_k2;

    float4 areg[8];

#pragma unroll 1
    for (int nc = 0; nc < 4; ++nc) {
        float c[4][4][4];
#pragma unroll
        for (int mt = 0; mt < 4; ++mt)
#pragma unroll
            for (int nt = 0; nt < 4; ++nt)
#pragma unroll
                for (int e = 0; e < 4; ++e) c[mt][nt][e] = 0.0f;

        // ---- prologue: load stage 0 ----
        {
            const int k0 = 0, n0 = nc * 128;
#pragma unroll
            for (int it = 0; it < 4; ++it) {
                int v = tid + it * 256, r = v >> 3, j = v & 7;
                uint32_t d = sb + OFF_BUF + (uint32_t)ABYTES + (uint32_t)(r * RS + j * 16);
                cp16(d, W1h + (size_t)(n0 + r) * D_ + k0 + j * 8);
            }
            asm volatile("cp.async.commit_group;" ::: "memory");
#pragma unroll
            for (int it = 0; it < 8; ++it) {
                int v = tid + it * 256, r = v >> 4, c4 = v & 15;
                areg[it] = *reinterpret_cast<const float4*>(
                    V + (size_t)(row0 + r) * D_ + k0 + c4 * 4);
            }
#pragma unroll
            for (int it = 0; it < 8; ++it) {
                int v = tid + it * 256, r = v >> 4, c4 = v & 15;
                __half2 p0 = make_half2(__float2half(areg[it].x), __float2half(areg[it].y));
                __half2 p1 = make_half2(__float2half(areg[it].z), __float2half(areg[it].w));
                uint2 hp = make_uint2(*reinterpret_cast<uint32_t*>(&p0),
                                      *reinterpret_cast<uint32_t*>(&p1));
                *reinterpret_cast<uint2*>(sm + OFF_BUF + r * RS + c4 * 8) = hp;
            }
            asm volatile("cp.async.wait_group 0;" ::: "memory");
            __syncthreads();
        }

        // ---- main loop over 12 K-stages ----
#pragma unroll 1
        for (int s = 0; s < 12; ++s) {
            const uint32_t curOff = OFF_BUF + (uint32_t)(s & 1) * BUFB;
            const uint32_t nxtOff = OFF_BUF + (uint32_t)((s + 1) & 1) * BUFB;

            if (s < 11) {
                const int k0 = (s + 1) * 64, n0 = nc * 128;
#pragma unroll
                for (int it = 0; it < 4; ++it) {
                    int v = tid + it * 256, r = v >> 3, j = v & 7;
                    uint32_t d = sb + nxtOff + (uint32_t)ABYTES + (uint32_t)(r * RS + j * 16);
                    cp16(d, W1h + (size_t)(n0 + r) * D_ + k0 + j * 8);
                }
                asm volatile("cp.async.commit_group;" ::: "memory");
#pragma unroll
                for (int it = 0; it < 8; ++it) {
                    int v = tid + it * 256, r = v >> 4, c4 = v & 15;
                    areg[it] = *reinterpret_cast<const float4*>(
                        V + (size_t)(row0 + r) * D_ + k0 + c4 * 4);
                }
            }

            // ---- compute 4 x k16 from current buffers ----
            const uint32_t Ah = sb + curOff;
            const uint32_t Bh = sb + curOff + (uint32_t)ABYTES;
#pragma unroll
            for (int kk = 0; kk < 4; ++kk) {
                const uint32_t kb = (uint32_t)(kk * 32);
                uint32_t ah[4][4];
#pragma unroll
                for (int mt = 0; mt < 4; ++mt)
                    ldsm4(ah[mt], Ah + aoff + (uint32_t)(mt * 16 * RS) + kb);
                uint32_t bh[2][4];
#pragma unroll
                for (int p = 0; p < 2; ++p)
                    ldsm4(bh[p], Bh + boff + (uint32_t)(p * 16 * RS) + kb);
#pragma unroll
                for (int mt = 0; mt < 4; ++mt)
#pragma unroll
                    for (int nt = 0; nt < 4; ++nt)
                        mma16816(c[mt][nt], ah[mt],
                                 bh[nt >> 1][(nt & 1) * 2], bh[nt >> 1][(nt & 1) * 2 + 1]);
            }

            if (s < 11) {
#pragma unroll
                for (int it = 0; it < 8; ++it) {
                    int v = tid + it * 256, r = v >> 4, c4 = v & 15;
                    __half2 p0 = make_half2(__float2half(areg[it].x), __float2half(areg[it].y));
                    __half2 p1 = make_half2(__float2half(areg[it].z), __float2half(areg[it].w));
                    uint2 hp = make_uint2(*reinterpret_cast<uint32_t*>(&p0),
                                          *reinterpret_cast<uint32_t*>(&p1));
                    *reinterpret_cast<uint2*>(sm + nxtOff + r * RS + c4 * 8) = hp;
                }
                asm volatile("cp.async.wait_group 0;" ::: "memory");
            }
            __syncthreads();
        }

        // ---- epilogue: accumulate partial g into gs ----
#pragma unroll
        for (int mt = 0; mt < 4; ++mt) {
            float s0 = 0.0f, s1 = 0.0f;
#pragma unroll
            for (int nt = 0; nt < 4; ++nt) {
                int n = nc * 128 + wn * 32 + nt * 8 + (lane & 3) * 2;
                float w0 = w2s[n],     w1v = w2s[n + 1];
                float q0 = b1s[n],     q1  = b1s[n + 1];
                s0 += w0 * tanhf(c[mt][nt][0] + q0) + w1v * tanhf(c[mt][nt][1] + q1);
                s1 += w0 * tanhf(c[mt][nt][2] + q0) + w1v * tanhf(c[mt][nt][3] + q1);
            }
            s0 += __shfl_xor_sync(0xffffffffu, s0, 1);
            s0 += __shfl_xor_sync(0xffffffffu, s0, 2);
            s1 += __shfl_xor_sync(0xffffffffu, s1, 1);
            s1 += __shfl_xor_sync(0xffffffffu, s1, 2);
            if ((lane & 3) == 0) {
                int m = wm * 64 + mt * 16 + (lane >> 2);
                gs[wn * 128 + m]     += s0;
                gs[wn * 128 + m + 8] += s1;
            }
        }
    }

    __syncthreads();
    if (tid < 128)
        g_buf[row0 + tid] = gs[tid] + gs[128 + tid] + gs[256 + tid] + gs[384 + tid]
                          + B2[0];
}

// ---------------------------------------------------------------------------
// attn_kernel: per-batch attention + classifier, 512 threads, small smem
// (high occupancy; entity pass re-reads V through L2).
// Uses ms == 1/61 identity to skip the first softmax.
// ---------------------------------------------------------------------------
__global__ __launch_bounds__(512)
void attn_kernel(const float* __restrict__ T,
                 const float* __restrict__ V,
                 const int*   __restrict__ ids,
                 const float* __restrict__ CW,
                 const float* __restrict__ CB,
                 float*       __restrict__ out)
{
    __shared__ float Th[D_], Tt[D_];
    __shared__ float ent[2 * D_];
    __shared__ float sc_h[S_ + 3], sc_t[S_ + 3], gsA[S_ + 3];
    __shared__ float wh[S_ + 3], wt[S_ + 3];
    __shared__ int   hidx, tidx;

    const int b   = blockIdx.x;
    const int tid = threadIdx.x;
    const int warp = tid >> 5, lane = tid & 31;

    if (tid == 0) { hidx = 0; tidx = 0; }
    __syncthreads();

    if (tid < S_) {
        int id = ids[b * S_ + tid];
        if (id == HEAD_TOK) hidx = tid;
        if (id == TAIL_TOK) tidx = tid;
        gsA[tid] = g_buf[b * S_ + tid];
    }
    __syncthreads();

    const int hq = hidx, tq = tidx;
    for (int d = tid; d < D_; d += 512) {
        Th[d] = T[((size_t)b * S_ + hq) * D_ + d];
        Tt[d] = T[((size_t)b * S_ + tq) * D_ + d];
    }
    __syncthreads();

    // raw scores for the two needed query rows (V streamed from gmem)
    for (int k = warp; k < S_; k += 16) {
        const float* vk = V + ((size_t)b * S_ + k) * D_;
        float sh = 0.0f, st = 0.0f;
#pragma unroll 6
        for (int d = lane; d < D_; d += 32) {
            float v = vk[d];
            sh = fmaf(Th[d], v, sh);
            st = fmaf(Tt[d], v, st);
        }
#pragma unroll
        for (int o = 16; o; o >>= 1) {
            sh += __shfl_xor_sync(0xffffffffu, sh, o);
            st += __shfl_xor_sync(0xffffffffu, st, o);
        }
        if (lane == 0) { sc_h[k] = sh; sc_t[k] = st; }
    }
    __syncthreads();

    // gated softmax: a = (scores*(1-g) + g/61) / sqrt(768)
    if (warp < 2) {
        const float* sc = warp ? sc_t : sc_h;
        float*       w  = warp ? wt   : wh;
        const float scale = sqrtf((float)D_);
        const float inv61 = 1.0f / (float)S_;

        int k0 = lane, k1 = lane + 32;
        float a0 = -1e30f, a1 = -1e30f;
        if (k0 < S_) a0 = (sc[k0] * (1.0f - gsA[k0]) + gsA[k0] * inv61) / scale;
        if (k1 < S_) a1 = (sc[k1] * (1.0f - gsA[k1]) + gsA[k1] * inv61) / scale;
        float m = fmaxf(a0, a1);
#pragma unroll
        for (int o = 16; o; o >>= 1) m = fmaxf(m, __shfl_xor_sync(0xffffffffu, m, o));
        float e0 = (k0 < S_) ? expf(a0 - m) : 0.0f;
        float e1 = (k1 < S_) ? expf(a1 - m) : 0.0f;
        float s = e0 + e1;
#pragma unroll
        for (int o = 16; o; o >>= 1) s += __shfl_xor_sync(0xffffffffu, s, o);
        float inv = 1.0f / s;
        if (k0 < S_) w[k0] = e0 * inv;
        if (k1 < S_) w[k1] = e1 * inv;
    }
    __syncthreads();

    // entity vector: weighted sums over V keys (V re-read; L2-resident)
    for (int d = tid; d < D_; d += 512) {
        float ah = 0.0f, at = 0.0f;
        const float* vb = V + (size_t)b * S_ * D_ + d;
#pragma unroll 4
        for (int k = 0; k < S_; ++k) {
            float v = vb[(size_t)k * D_];
            ah = fmaf(wh[k], v, ah);
            at = fmaf(wt[k], v, at);
        }
        ent[d]      = ah;
        ent[D_ + d] = at;
    }
    __syncthreads();

    // classifier
    for (int l = warp; l < L_; l += 16) {
        const float* cw = CW + (size_t)l * (2 * D_);
        float s = 0.0f;
#pragma unroll 3
        for (int d = lane; d < 2 * D_; d += 32)
            s = fmaf(cw[d], ent[d], s);
#pragma unroll
        for (int o = 16; o; o >>= 1) s += __shfl_xor_sync(0xffffffffu, s, o);
        if (lane == 0) out[(size_t)b * L_ + l] = s + CB[l];
    }
}

// ---------------------------------------------------------------------------
extern "C" void kernel_launch(void* const* d_in, const int* in_sizes, int n_in,
                              void* d_out, int out_size)
{
    const float* T_recon = (const float*)d_in[0];
    const float* V_recon = (const float*)d_in[1];
    const int*   ids     = (const int*)  d_in[2];
    const float* fc1_w   = (const float*)d_in[3];
    const float* fc1_b   = (const float*)d_in[4];
    const float* fc2_w   = (const float*)d_in[5];
    const float* fc2_b   = (const float*)d_in[6];
    const float* clf_w   = (const float*)d_in[7];
    const float* clf_b   = (const float*)d_in[8];
    float* out = (float*)d_out;

    cudaFuncSetAttribute(gate_kernel,
                         cudaFuncAttributeMaxDynamicSharedMemorySize, GATE_SMEM);

    prep_kernel<<<H_ * D_ / 4 / 256, 256>>>(fc1_w);
    gate_kernel<<<MTOT / 128, 256, GATE_SMEM>>>(V_recon, fc1_b, fc2_w, fc2_b);
    attn_kernel<<<B_, 512>>>(T_recon, V_recon, ids, clf_w, clf_b, out);
}